// round 2
// baseline (speedup 1.0000x reference)
#include <cuda_runtime.h>
#include <cuda_bf16.h>
#include <cstdint>

#define BB 256
#define SS 1024
#define DD 64
#define HH 128
#define G  4      // batches per recurrence CTA
#define R1 32     // rows per xp CTA
#define WPAD 132  // padded Whh row stride (floats)

// ---------------- scratch (device globals; no allocation) ----------------
__device__ float g_xp[2ull * BB * SS * HH];    // 268 MB: input projections per dir
__device__ float g_dot[2ull * BB * SS];        // per-direction FC partials
__device__ float g_wt[2 * DD * HH];            // Wih transposed: [dir][d][j]
__device__ float g_bias[2 * HH];               // bih + bhh per dir

// ---------------- helpers ----------------
__device__ __forceinline__ float ftanh(float x) {
    float y = 2.0f * x;
    y = fminf(fmaxf(y, -30.0f), 30.0f);
    float e = __expf(y);
    return (e - 1.0f) / (e + 1.0f);
}

// ---------------- prep: transpose Wih, fold biases ----------------
__global__ void prep_kernel(const float* __restrict__ Wih_fw,
                            const float* __restrict__ bih_fw,
                            const float* __restrict__ bhh_fw,
                            const float* __restrict__ Wih_bw,
                            const float* __restrict__ bih_bw,
                            const float* __restrict__ bhh_bw) {
    int tid = threadIdx.x;
    for (int dir = 0; dir < 2; dir++) {
        const float* Wih = dir ? Wih_bw : Wih_fw;
        const float* bih = dir ? bih_bw : bih_fw;
        const float* bhh = dir ? bhh_bw : bhh_fw;
        for (int i = tid; i < DD * HH; i += blockDim.x) {
            int d = i / HH, j = i % HH;
            g_wt[dir * DD * HH + d * HH + j] = Wih[j * DD + d];
        }
        for (int i = tid; i < HH; i += blockDim.x)
            g_bias[dir * HH + i] = bih[i] + bhh[i];
    }
}

// ---------------- kernel 1: xp = inputs @ Wih^T + bias ----------------
__global__ void __launch_bounds__(128) xp_kernel(const float* __restrict__ inp) {
    __shared__ __align__(16) float in_s[R1 * DD];   // 8 KB
    __shared__ __align__(16) float w_s[DD * HH];    // 32 KB, layout [d][j]

    const int j   = threadIdx.x;
    const int dir = blockIdx.y;
    const size_t r0 = (size_t)blockIdx.x * R1;

    const float* wt = g_wt + dir * DD * HH;
    for (int i = j; i < DD * HH; i += 128) w_s[i] = wt[i];
    for (int i = j; i < R1 * DD; i += 128) in_s[i] = inp[r0 * DD + i];
    const float bj = g_bias[dir * HH + j];
    __syncthreads();

    float acc[R1];
#pragma unroll
    for (int r = 0; r < R1; r++) acc[r] = 0.0f;

#pragma unroll 4
    for (int d = 0; d < DD; d += 4) {
        const float w0 = w_s[(d + 0) * HH + j];
        const float w1 = w_s[(d + 1) * HH + j];
        const float w2 = w_s[(d + 2) * HH + j];
        const float w3 = w_s[(d + 3) * HH + j];
#pragma unroll
        for (int r = 0; r < R1; r++) {
            const float4 v = *(const float4*)(in_s + r * DD + d);
            float a = acc[r];
            a = fmaf(w0, v.x, a);
            a = fmaf(w1, v.y, a);
            a = fmaf(w2, v.z, a);
            a = fmaf(w3, v.w, a);
            acc[r] = a;
        }
    }

    float* out = g_xp + ((size_t)dir * BB * SS + r0) * HH;
#pragma unroll
    for (int r = 0; r < R1; r++) out[(size_t)r * HH + j] = acc[r] + bj;
}

// ---------------- kernel 2: recurrence + fused FC dot ----------------
__global__ void __launch_bounds__(128) rnn_kernel(const float* __restrict__ Whh_fw,
                                                  const float* __restrict__ Whh_bw,
                                                  const float* __restrict__ fcW) {
    extern __shared__ __align__(16) float sm[];
    float* w_s = sm;                       // 128*132 floats
    float* h_s = sm + HH * WPAD;           // 2*G*128 floats (double buffer)
    float* red = h_s + 2 * G * HH;         // 2*16 floats (double buffer)

    const int j    = threadIdx.x;
    const int lane = j & 31;
    const int wid  = j >> 5;
    const int dir  = blockIdx.y;
    const int b0   = blockIdx.x * G;

    const float* Whh = dir ? Whh_bw : Whh_fw;
    for (int i = j; i < HH * HH; i += 128) {
        int row = i >> 7, col = i & 127;
        w_s[row * WPAD + col] = Whh[i];
    }
#pragma unroll
    for (int g = 0; g < G; g++) {
        h_s[g * HH + j] = 0.0f;
        h_s[(G + g) * HH + j] = 0.0f;
    }
    const float fcw = fcW[dir * HH + j];

    const int p0    = dir ? (SS - 1) : 0;
    const int dstep = dir ? -1 : 1;
    const long stepH = (long)dstep * HH;

    const float* xp0 = g_xp + (((size_t)dir * BB + b0 + 0) * SS + p0) * HH + j;
    const float* xp1 = g_xp + (((size_t)dir * BB + b0 + 1) * SS + p0) * HH + j;
    const float* xp2 = g_xp + (((size_t)dir * BB + b0 + 2) * SS + p0) * HH + j;
    const float* xp3 = g_xp + (((size_t)dir * BB + b0 + 3) * SS + p0) * HH + j;

    __syncthreads();

    float x0 = *xp0, x1 = *xp1, x2 = *xp2, x3 = *xp3;

    const float* wr = w_s + j * WPAD;
    int cur = 0;
    int p = p0;

    for (int t = 0; t < SS; t++) {
        float a0 = x0, a1 = x1, a2 = x2, a3 = x3;

        // prefetch next timestep xp (hides DRAM/L2 latency under k-loop)
        if (t + 1 < SS) {
            xp0 += stepH; xp1 += stepH; xp2 += stepH; xp3 += stepH;
            x0 = *xp0; x1 = *xp1; x2 = *xp2; x3 = *xp3;
        }

        const float* hc = h_s + cur * G * HH;
#pragma unroll
        for (int k = 0; k < HH; k += 4) {
            const float4 w = *(const float4*)(wr + k);
            float4 v;
            v = *(const float4*)(hc + 0 * HH + k);
            a0 = fmaf(w.x, v.x, a0); a0 = fmaf(w.y, v.y, a0);
            a0 = fmaf(w.z, v.z, a0); a0 = fmaf(w.w, v.w, a0);
            v = *(const float4*)(hc + 1 * HH + k);
            a1 = fmaf(w.x, v.x, a1); a1 = fmaf(w.y, v.y, a1);
            a1 = fmaf(w.z, v.z, a1); a1 = fmaf(w.w, v.w, a1);
            v = *(const float4*)(hc + 2 * HH + k);
            a2 = fmaf(w.x, v.x, a2); a2 = fmaf(w.y, v.y, a2);
            a2 = fmaf(w.z, v.z, a2); a2 = fmaf(w.w, v.w, a2);
            v = *(const float4*)(hc + 3 * HH + k);
            a3 = fmaf(w.x, v.x, a3); a3 = fmaf(w.y, v.y, a3);
            a3 = fmaf(w.z, v.z, a3); a3 = fmaf(w.w, v.w, a3);
        }

        const float v0 = ftanh(a0);
        const float v1 = ftanh(a1);
        const float v2 = ftanh(a2);
        const float v3 = ftanh(a3);

        float* hn = h_s + (cur ^ 1) * G * HH;
        hn[0 * HH + j] = v0;
        hn[1 * HH + j] = v1;
        hn[2 * HH + j] = v2;
        hn[3 * HH + j] = v3;

        // fused FC: dot over j of v_g * fcw_j
        float s0 = v0 * fcw, s1 = v1 * fcw, s2 = v2 * fcw, s3 = v3 * fcw;
#pragma unroll
        for (int off = 16; off > 0; off >>= 1) {
            s0 += __shfl_xor_sync(0xFFFFFFFFu, s0, off);
            s1 += __shfl_xor_sync(0xFFFFFFFFu, s1, off);
            s2 += __shfl_xor_sync(0xFFFFFFFFu, s2, off);
            s3 += __shfl_xor_sync(0xFFFFFFFFu, s3, off);
        }
        float* rb = red + (t & 1) * 16;
        if (lane == 0) {
            rb[wid * 4 + 0] = s0;
            rb[wid * 4 + 1] = s1;
            rb[wid * 4 + 2] = s2;
            rb[wid * 4 + 3] = s3;
        }
        __syncthreads();

        if (j < G) {
            const float d = rb[j] + rb[4 + j] + rb[8 + j] + rb[12 + j];
            g_dot[((size_t)dir * BB + b0 + j) * SS + p] = d;
        }

        cur ^= 1;
        p += dstep;
    }
}

// ---------------- kernel 3: combine directions + fc_b ----------------
__global__ void fc_kernel(float* __restrict__ out, const float* __restrict__ fcb) {
    int i = blockIdx.x * blockDim.x + threadIdx.x;
    if (i < BB * SS) out[i] = g_dot[i] + g_dot[(size_t)BB * SS + i] + fcb[0];
}

// ---------------- launch ----------------
extern "C" void kernel_launch(void* const* d_in, const int* in_sizes, int n_in,
                              void* d_out, int out_size) {
    const float* inputs = (const float*)d_in[0];
    const float* Wih_fw = (const float*)d_in[1];
    const float* Whh_fw = (const float*)d_in[2];
    const float* bih_fw = (const float*)d_in[3];
    const float* bhh_fw = (const float*)d_in[4];
    const float* Wih_bw = (const float*)d_in[5];
    const float* Whh_bw = (const float*)d_in[6];
    const float* bih_bw = (const float*)d_in[7];
    const float* bhh_bw = (const float*)d_in[8];
    const float* fc_W   = (const float*)d_in[9];
    const float* fc_b   = (const float*)d_in[10];
    float* out = (float*)d_out;

    const int smem2 = (HH * WPAD + 2 * G * HH + 32) * (int)sizeof(float); // ~71.9 KB
    cudaFuncSetAttribute(rnn_kernel, cudaFuncAttributeMaxDynamicSharedMemorySize, smem2);

    prep_kernel<<<1, 256>>>(Wih_fw, bih_fw, bhh_fw, Wih_bw, bih_bw, bhh_bw);
    xp_kernel<<<dim3((BB * SS) / R1, 2), 128>>>(inputs);
    rnn_kernel<<<dim3(BB / G, 2), 128, smem2>>>(Whh_fw, Whh_bw, fc_W);
    fc_kernel<<<(BB * SS + 255) / 256, 256>>>(out, fc_b);
}

// round 4
// speedup vs baseline: 1.3968x; 1.3968x over previous
#include <cuda_runtime.h>
#include <cuda_bf16.h>
#include <cstdint>

#define BB 256
#define SS 1024
#define DD 64
#define HH 128
#define G  4      // batches per rnn CTA
#define XR 64     // rows per xp CTA

typedef unsigned long long u64;

// ---------------- scratch (device globals; no allocation) ----------------
__device__ float g_xp[2ull * BB * SS * HH];    // input projections per dir
__device__ float g_dot[2ull * BB * SS];        // per-direction FC partials

// ---------------- f32x2 helpers ----------------
__device__ __forceinline__ u64 pack2(float a, float b) {
    u64 r; asm("mov.b64 %0, {%1, %2};" : "=l"(r) : "f"(a), "f"(b)); return r;
}
__device__ __forceinline__ void unpack2(u64 v, float& a, float& b) {
    asm("mov.b64 {%0, %1}, %2;" : "=f"(a), "=f"(b) : "l"(v));
}
__device__ __forceinline__ void ffma2(u64& d, u64 a, u64 b) {
    asm("fma.rn.f32x2 %0, %1, %2, %0;" : "+l"(d) : "l"(a), "l"(b));
}

__device__ __forceinline__ float ftanh(float x) {
    float y = fminf(fmaxf(2.0f * x, -30.0f), 30.0f);
    float e = __expf(y);
    return __fdividef(e - 1.0f, e + 1.0f);
}

// ---------------- kernel 1: xp = inputs @ Wih^T + (bih+bhh) ----------------
// Thread j holds Wih row j (64 floats) in 32 packed f32x2 registers.
__global__ void __launch_bounds__(128) xp_kernel(
    const float* __restrict__ inp,
    const float* __restrict__ Wih_fw, const float* __restrict__ bih_fw,
    const float* __restrict__ bhh_fw,
    const float* __restrict__ Wih_bw, const float* __restrict__ bih_bw,
    const float* __restrict__ bhh_bw)
{
    __shared__ __align__(16) float in_s[XR * DD];   // 16 KB

    const int j   = threadIdx.x;
    const int dir = blockIdx.y;
    const size_t r0 = (size_t)blockIdx.x * XR;

    const float* Wih = dir ? Wih_bw : Wih_fw;
    const float* bih = dir ? bih_bw : bih_fw;
    const float* bhh = dir ? bhh_bw : bhh_fw;

    u64 w[32];
    {
        const float* wr = Wih + j * DD;
#pragma unroll
        for (int i = 0; i < 16; i++) {
            float4 v = *(const float4*)(wr + 4 * i);
            w[2 * i]     = pack2(v.x, v.y);
            w[2 * i + 1] = pack2(v.z, v.w);
        }
    }
    const float bj = bih[j] + bhh[j];

    // stage inputs: XR*DD floats = 1024 float4, 128 threads -> 8 each
    {
        const float4* src = (const float4*)(inp + r0 * DD);
        float4* dst = (float4*)in_s;
#pragma unroll
        for (int i = 0; i < 8; i++) dst[j + i * 128] = src[j + i * 128];
    }
    __syncthreads();

    float* out = g_xp + ((size_t)dir * BB * SS + r0) * HH + j;
#pragma unroll 1
    for (int rb = 0; rb < XR; rb += 4) {
        u64 a0 = 0, a1 = 0, a2 = 0, a3 = 0;
        const float* p = in_s + rb * DD;
#pragma unroll
        for (int i = 0; i < 16; i++) {
            ulonglong2 v0 = *(const ulonglong2*)(p + 0 * DD + 4 * i);
            ffma2(a0, w[2 * i], v0.x); ffma2(a0, w[2 * i + 1], v0.y);
            ulonglong2 v1 = *(const ulonglong2*)(p + 1 * DD + 4 * i);
            ffma2(a1, w[2 * i], v1.x); ffma2(a1, w[2 * i + 1], v1.y);
            ulonglong2 v2 = *(const ulonglong2*)(p + 2 * DD + 4 * i);
            ffma2(a2, w[2 * i], v2.x); ffma2(a2, w[2 * i + 1], v2.y);
            ulonglong2 v3 = *(const ulonglong2*)(p + 3 * DD + 4 * i);
            ffma2(a3, w[2 * i], v3.x); ffma2(a3, w[2 * i + 1], v3.y);
        }
        float lo, hi;
        unpack2(a0, lo, hi); out[(size_t)(rb + 0) * HH] = lo + hi + bj;
        unpack2(a1, lo, hi); out[(size_t)(rb + 1) * HH] = lo + hi + bj;
        unpack2(a2, lo, hi); out[(size_t)(rb + 2) * HH] = lo + hi + bj;
        unpack2(a3, lo, hi); out[(size_t)(rb + 3) * HH] = lo + hi + bj;
    }
}

// ---------------- kernel 2: recurrence + fused FC dot ----------------
// 256 threads: tid = 2*j + ks. Thread (j,ks) owns Whh[j][k] for
// k in {8i+4ks+c : i=0..15, c=0..3} as 32 packed f32x2 registers.
__global__ void __launch_bounds__(256, 1) rnn_kernel(
    const float* __restrict__ Whh_fw,
    const float* __restrict__ Whh_bw,
    const float* __restrict__ fcW)
{
    __shared__ __align__(16) float h_s[2][G][HH];   // 4 KB double-buffered state
    __shared__ float red[2][8 * G];                 // per-warp FC partials

    const int tid  = threadIdx.x;
    const int j    = tid >> 1;
    const int ks   = tid & 1;
    const int lane = tid & 31;
    const int wrp  = tid >> 5;
    const int dir  = blockIdx.y;
    const int b0   = blockIdx.x * G;

    // weights -> registers (one time)
    const float* Whh = dir ? Whh_bw : Whh_fw;
    u64 w[32];
    {
        const float* wr = Whh + j * HH + 4 * ks;
#pragma unroll
        for (int i = 0; i < 16; i++) {
            float4 v = *(const float4*)(wr + 8 * i);
            w[2 * i]     = pack2(v.x, v.y);
            w[2 * i + 1] = pack2(v.z, v.w);
        }
    }
    const float fcw = fcW[dir * HH + j];

    // zero initial h buffer (buffer 0 only; buffer 1 written at t=0)
    for (int i = tid; i < G * HH; i += 256) ((float*)h_s)[i] = 0.0f;

    const int p0    = dir ? (SS - 1) : 0;
    const int dstep = dir ? -1 : 1;
    const long stepH = (long)dstep * HH;

    const float* x0p = g_xp + (((size_t)dir * BB + b0 + 0) * SS + p0) * HH + j;
    const float* x1p = g_xp + (((size_t)dir * BB + b0 + 1) * SS + p0) * HH + j;
    const float* x2p = g_xp + (((size_t)dir * BB + b0 + 2) * SS + p0) * HH + j;
    const float* x3p = g_xp + (((size_t)dir * BB + b0 + 3) * SS + p0) * HH + j;

    __syncthreads();

    float x0 = *x0p, x1 = *x1p, x2 = *x2p, x3 = *x3p;
    float ps0 = 0.0f, ps1 = 0.0f, ps2 = 0.0f, ps3 = 0.0f;  // FC partials (step t-1)

    int cur = 0;
    int p = p0;

#pragma unroll 1
    for (int t = 0; t < SS; t++) {
        // ---- FC reduce for previous step (latency overlaps FMA loop) ----
        float r0 = ps0, r1 = ps1, r2 = ps2, r3 = ps3;
#pragma unroll
        for (int off = 2; off <= 16; off <<= 1) {
            r0 += __shfl_xor_sync(0xFFFFFFFFu, r0, off);
            r1 += __shfl_xor_sync(0xFFFFFFFFu, r1, off);
            r2 += __shfl_xor_sync(0xFFFFFFFFu, r2, off);
            r3 += __shfl_xor_sync(0xFFFFFFFFu, r3, off);
        }

        // ---- prefetch next xp ----
        float nx0, nx1, nx2, nx3;
        if (t + 1 < SS) {
            x0p += stepH; x1p += stepH; x2p += stepH; x3p += stepH;
            nx0 = *x0p; nx1 = *x1p; nx2 = *x2p; nx3 = *x3p;
        }

        // ---- matvec: all weights in registers, h broadcast from smem ----
        u64 a0 = 0, a1 = 0, a2 = 0, a3 = 0;
        const float* hcp = &h_s[cur][0][4 * ks];
#pragma unroll
        for (int i = 0; i < 16; i++) {
            ulonglong2 h0 = *(const ulonglong2*)(hcp + 0 * HH + 8 * i);
            ffma2(a0, w[2 * i], h0.x); ffma2(a0, w[2 * i + 1], h0.y);
            ulonglong2 h1 = *(const ulonglong2*)(hcp + 1 * HH + 8 * i);
            ffma2(a1, w[2 * i], h1.x); ffma2(a1, w[2 * i + 1], h1.y);
            ulonglong2 h2 = *(const ulonglong2*)(hcp + 2 * HH + 8 * i);
            ffma2(a2, w[2 * i], h2.x); ffma2(a2, w[2 * i + 1], h2.y);
            ulonglong2 h3 = *(const ulonglong2*)(hcp + 3 * HH + 8 * i);
            ffma2(a3, w[2 * i], h3.x); ffma2(a3, w[2 * i + 1], h3.y);
        }

        // ---- finalize: combine halves, cross-ks shfl, tanh ----
        float lo, hi;
        unpack2(a0, lo, hi); float s0 = lo + hi;
        unpack2(a1, lo, hi); float s1 = lo + hi;
        unpack2(a2, lo, hi); float s2 = lo + hi;
        unpack2(a3, lo, hi); float s3 = lo + hi;
        s0 += __shfl_xor_sync(0xFFFFFFFFu, s0, 1);
        s1 += __shfl_xor_sync(0xFFFFFFFFu, s1, 1);
        s2 += __shfl_xor_sync(0xFFFFFFFFu, s2, 1);
        s3 += __shfl_xor_sync(0xFFFFFFFFu, s3, 1);

        const float v0 = ftanh(s0 + x0);
        const float v1 = ftanh(s1 + x1);
        const float v2 = ftanh(s2 + x2);
        const float v3 = ftanh(s3 + x3);

        // ---- store new h (split stores across ks lanes) ----
        float* hnp = &h_s[cur ^ 1][0][0];
        if (ks == 0) {
            hnp[0 * HH + j] = v0;
            hnp[1 * HH + j] = v1;
        } else {
            hnp[2 * HH + j] = v2;
            hnp[3 * HH + j] = v3;
        }

        // new FC partials for this step
        ps0 = v0 * fcw; ps1 = v1 * fcw; ps2 = v2 * fcw; ps3 = v3 * fcw;

        // publish previous step's warp partials
        if (lane == 0) {
            red[t & 1][wrp * 4 + 0] = r0;
            red[t & 1][wrp * 4 + 1] = r1;
            red[t & 1][wrp * 4 + 2] = r2;
            red[t & 1][wrp * 4 + 3] = r3;
        }

        __syncthreads();

        // gather prev step's dot (4 threads)
        if (tid < G && t > 0) {
            const float* rb = red[t & 1];
            float d = 0.0f;
#pragma unroll
            for (int ww = 0; ww < 8; ww++) d += rb[ww * 4 + tid];
            g_dot[((size_t)dir * BB + b0 + tid) * SS + (p - dstep)] = d;
        }

        x0 = nx0; x1 = nx1; x2 = nx2; x3 = nx3;
        cur ^= 1;
        p += dstep;
    }

    // ---- epilogue: flush FC dot for final step ----
#pragma unroll
    for (int off = 2; off <= 16; off <<= 1) {
        ps0 += __shfl_xor_sync(0xFFFFFFFFu, ps0, off);
        ps1 += __shfl_xor_sync(0xFFFFFFFFu, ps1, off);
        ps2 += __shfl_xor_sync(0xFFFFFFFFu, ps2, off);
        ps3 += __shfl_xor_sync(0xFFFFFFFFu, ps3, off);
    }
    if (lane == 0) {
        red[0][wrp * 4 + 0] = ps0;
        red[0][wrp * 4 + 1] = ps1;
        red[0][wrp * 4 + 2] = ps2;
        red[0][wrp * 4 + 3] = ps3;
    }
    __syncthreads();
    if (tid < G) {
        const float* rb = red[0];
        float d = 0.0f;
#pragma unroll
        for (int ww = 0; ww < 8; ww++) d += rb[ww * 4 + tid];
        g_dot[((size_t)dir * BB + b0 + tid) * SS + (p - dstep)] = d;
    }
}

// ---------------- kernel 3: combine directions + fc_b ----------------
__global__ void fc_kernel(float* __restrict__ out, const float* __restrict__ fcb) {
    int i = blockIdx.x * blockDim.x + threadIdx.x;
    if (i < BB * SS) out[i] = g_dot[i] + g_dot[(size_t)BB * SS + i] + fcb[0];
}

// ---------------- launch ----------------
extern "C" void kernel_launch(void* const* d_in, const int* in_sizes, int n_in,
                              void* d_out, int out_size) {
    const float* inputs = (const float*)d_in[0];
    const float* Wih_fw = (const float*)d_in[1];
    const float* Whh_fw = (const float*)d_in[2];
    const float* bih_fw = (const float*)d_in[3];
    const float* bhh_fw = (const float*)d_in[4];
    const float* Wih_bw = (const float*)d_in[5];
    const float* Whh_bw = (const float*)d_in[6];
    const float* bih_bw = (const float*)d_in[7];
    const float* bhh_bw = (const float*)d_in[8];
    const float* fc_W   = (const float*)d_in[9];
    const float* fc_b   = (const float*)d_in[10];
    float* out = (float*)d_out;

    xp_kernel<<<dim3((BB * SS) / XR, 2), 128>>>(inputs,
                                                Wih_fw, bih_fw, bhh_fw,
                                                Wih_bw, bih_bw, bhh_bw);
    rnn_kernel<<<dim3(BB / G, 2), 256>>>(Whh_fw, Whh_bw, fc_W);
    fc_kernel<<<(BB * SS + 255) / 256, 256>>>(out, fc_b);
}